// round 1
// baseline (speedup 1.0000x reference)
#include <cuda_runtime.h>
#include <math.h>

#define S_LEN 4096
#define HID 2048
#define NH 16
#define NKV 4
#define DH 128
#define BLK 64
#define MSK 32
#define KTOP 8
#define NBLK 64   // S_LEN / BLK

// ---------------- scratch (static device allocations; no cudaMalloc) ----------------
__device__ float g_q[S_LEN * NH * DH];      // [s][h*128+d]  32 MB
__device__ float g_k[S_LEN * NKV * DH];     // [s][kvh*128+d] 8 MB
__device__ float g_v[S_LEN * NKV * DH];     // 8 MB
__device__ float g_att[S_LEN * NH * DH];    // attention output, [s][h*128+d] 32 MB
__device__ float g_sq[NH * NBLK * MSK];
__device__ float g_sk[NKV * NBLK * MSK];
__device__ int   g_idx[NH * NBLK * KTOP];
__device__ float2 g_cs[S_LEN * 64];         // cos/sin table

// ---------------- generic tiled SGEMM: C[M,N] = A[M,K] @ B[K,N], row-major ----------------
__global__ __launch_bounds__(256) void gemm_kernel(const float* __restrict__ A,
                                                   const float* __restrict__ B,
                                                   float* __restrict__ C,
                                                   int M, int N, int K) {
    __shared__ float As[16][132];   // As[k][m], padded
    __shared__ float Bs[16][132];   // Bs[k][n], padded
    const int bm = blockIdx.y * 128;
    const int bn = blockIdx.x * 128;
    const int t = threadIdx.x;
    const int tm = (t >> 4) << 3;   // 0..120
    const int tn = (t & 15) << 3;   // 0..120

    float acc[8][8];
#pragma unroll
    for (int i = 0; i < 8; i++)
#pragma unroll
        for (int j = 0; j < 8; j++) acc[i][j] = 0.f;

    for (int k0 = 0; k0 < K; k0 += 16) {
        // load A tile (128 rows x 16 k), transposed into As[k][m]
#pragma unroll
        for (int i = 0; i < 2; i++) {
            int li = t + i * 256;          // 0..511
            int r  = li >> 2;              // 0..127
            int c4 = (li & 3) << 2;        // 0,4,8,12
            float4 a = *(const float4*)(A + (size_t)(bm + r) * K + k0 + c4);
            As[c4 + 0][r] = a.x; As[c4 + 1][r] = a.y;
            As[c4 + 2][r] = a.z; As[c4 + 3][r] = a.w;
        }
        // load B tile (16 k x 128 n)
#pragma unroll
        for (int i = 0; i < 2; i++) {
            int li = t + i * 256;
            int r  = li >> 5;              // 0..15
            int c4 = (li & 31) << 2;       // 0..124
            *(float4*)&Bs[r][c4] = *(const float4*)(B + (size_t)(k0 + r) * N + bn + c4);
        }
        __syncthreads();
#pragma unroll
        for (int kk = 0; kk < 16; kk++) {
            float ar[8], br[8];
            *(float4*)(ar)     = *(float4*)&As[kk][tm];
            *(float4*)(ar + 4) = *(float4*)&As[kk][tm + 4];
            *(float4*)(br)     = *(float4*)&Bs[kk][tn];
            *(float4*)(br + 4) = *(float4*)&Bs[kk][tn + 4];
#pragma unroll
            for (int i = 0; i < 8; i++)
#pragma unroll
                for (int j = 0; j < 8; j++)
                    acc[i][j] = fmaf(ar[i], br[j], acc[i][j]);
        }
        __syncthreads();
    }
#pragma unroll
    for (int i = 0; i < 8; i++) {
        float* cp = C + (size_t)(bm + tm + i) * N + bn + tn;
        float4 v0 = make_float4(acc[i][0], acc[i][1], acc[i][2], acc[i][3]);
        float4 v1 = make_float4(acc[i][4], acc[i][5], acc[i][6], acc[i][7]);
        *(float4*)(cp)     = v0;
        *(float4*)(cp + 4) = v1;
    }
}

// ---------------- cos/sin table (double precision for accuracy) ----------------
__global__ void cs_kernel(const int* __restrict__ pos_ids) {
    int idx = blockIdx.x * 256 + threadIdx.x;
    if (idx >= S_LEN * 64) return;
    int s = idx >> 6, i = idx & 63;
    double inv = exp(-(double)i * (log(10000.0) / 64.0));
    double f = (double)pos_ids[s] * inv;
    g_cs[idx] = make_float2((float)cos(f), (float)sin(f));
}

// ---------------- RoPE (in place) ----------------
__global__ void rope_kernel(float* __restrict__ x, int nheads) {
    int idx = blockIdx.x * 256 + threadIdx.x;
    int total = S_LEN * nheads * 64;
    if (idx >= total) return;
    int i = idx & 63;
    int h = (idx >> 6) % nheads;
    int s = idx / (64 * nheads);
    float2 cs = g_cs[s * 64 + i];
    float* p = x + (size_t)s * nheads * DH + h * DH;
    float x1 = p[i], x2 = p[i + 64];
    p[i]      = x1 * cs.x - x2 * cs.y;
    p[i + 64] = x2 * cs.x + x1 * cs.y;
}

// ---------------- sketch: dst[h][blk][m] = mean_block(x) @ H ----------------
__global__ void sketch_kernel(const float* __restrict__ x, const float* __restrict__ H,
                              float* __restrict__ dst, int nheads) {
    int blk = blockIdx.x, h = blockIdx.y;
    int t = threadIdx.x;  // 128
    __shared__ float xb[128];
    int stride = nheads * DH;
    const float* base = x + (size_t)blk * BLK * stride + h * DH + t;
    float s = 0.f;
    for (int r = 0; r < BLK; r++) s += base[(size_t)r * stride];
    xb[t] = s * (1.f / 64.f);
    __syncthreads();
    if (t < MSK) {
        float a = 0.f;
        for (int d = 0; d < DH; d++) a += xb[d] * H[d * MSK + t];
        dst[((size_t)h * NBLK + blk) * MSK + t] = a;
    }
}

// ---------------- top-k block selection ----------------
__global__ void topk_kernel() {
    int qb = blockIdx.x, h = blockIdx.y;
    int j = threadIdx.x;  // 0..63
    __shared__ float sc[64];
    float s;
    if (j > qb) {
        s = -1e9f;
    } else {
        const float* a = g_sq + ((size_t)h * NBLK + qb) * MSK;
        const float* b = g_sk + ((size_t)(h >> 2) * NBLK + j) * MSK;
        s = 0.f;
        for (int m = 0; m < MSK; m++) s += a[m] * b[m];
    }
    if (j == qb) s = 1e9f;
    sc[j] = s;
    __syncthreads();
    if (j == 0) {
        for (int tsel = 0; tsel < KTOP; tsel++) {
            float best = -3.4e38f;
            int bi = 0;
            for (int jj = 0; jj < 64; jj++) {
                if (sc[jj] > best) { best = sc[jj]; bi = jj; }
            }
            g_idx[((size_t)h * NBLK + qb) * KTOP + tsel] = bi;
            sc[bi] = -3.4e38f;
        }
    }
}

// ---------------- block-sparse flash attention ----------------
__global__ __launch_bounds__(256) void attn_kernel() {
    extern __shared__ float sm[];
    float* Qs  = sm;                 // 64 x 129
    float* KVs = Qs + 64 * 129;      // 64 x 129 (K then reused for V)
    float* SC  = KVs + 64 * 129;     // 64 x 65
    float* Mx  = SC + 64 * 65;       // 64
    float* Lw  = Mx + 64;            // 64
    float* Al  = Lw + 64;            // 64

    const int qb = blockIdx.x, h = blockIdx.y, kvh = h >> 2;
    const int t = threadIdx.x;
    const float scale = 0.08838834764831845f;  // 1/sqrt(128)

    // load Q block
#pragma unroll
    for (int i = 0; i < 8; i++) {
        int li = t + i * 256;
        int r = li >> 5, c = (li & 31) << 2;
        float4 a = *(const float4*)(g_q + (size_t)(qb * 64 + r) * HID + h * DH + c);
        float* dp = &Qs[r * 129 + c];
        dp[0] = a.x; dp[1] = a.y; dp[2] = a.z; dp[3] = a.w;
    }
    if (t < 64) { Mx[t] = -3.4e38f; Lw[t] = 0.f; }

    float o[32];
#pragma unroll
    for (int j = 0; j < 32; j++) o[j] = 0.f;

    const int q0 = (t >> 4) << 2;   // 0..60
    const int k0 = (t & 15) << 2;   // 0..60
    const int qq = t >> 2;          // 0..63
    const int ao = t & 3;           // 0..3

    for (int it = 0; it < KTOP; it++) {
        int ki = g_idx[((size_t)h * NBLK + qb) * KTOP + it];
        __syncthreads();  // previous iteration's KVs/SC readers done
        // load K block
#pragma unroll
        for (int i = 0; i < 8; i++) {
            int li = t + i * 256;
            int r = li >> 5, c = (li & 31) << 2;
            float4 a = *(const float4*)(g_k + (size_t)(ki * 64 + r) * (NKV * DH) + kvh * DH + c);
            float* dp = &KVs[r * 129 + c];
            dp[0] = a.x; dp[1] = a.y; dp[2] = a.z; dp[3] = a.w;
        }
        __syncthreads();
        // scores: 4x4 micro-tile per thread
        float acc[4][4];
#pragma unroll
        for (int i = 0; i < 4; i++)
#pragma unroll
            for (int j = 0; j < 4; j++) acc[i][j] = 0.f;
        for (int d = 0; d < DH; d++) {
            float qv[4], kv[4];
#pragma unroll
            for (int i = 0; i < 4; i++) qv[i] = Qs[(q0 + i) * 129 + d];
#pragma unroll
            for (int j = 0; j < 4; j++) kv[j] = KVs[(k0 + j) * 129 + d];
#pragma unroll
            for (int i = 0; i < 4; i++)
#pragma unroll
                for (int j = 0; j < 4; j++) acc[i][j] = fmaf(qv[i], kv[j], acc[i][j]);
        }
        const int kbase = ki * 64, qbase = qb * 64;
#pragma unroll
        for (int i = 0; i < 4; i++)
#pragma unroll
            for (int j = 0; j < 4; j++) {
                float val = (kbase + k0 + j <= qbase + q0 + i) ? acc[i][j] * scale : -1e9f;
                SC[(q0 + i) * 65 + k0 + j] = val;
            }
        __syncthreads();
        // online softmax update (one thread per query row)
        if (t < 64) {
            float mloc = -3.4e38f;
            for (int c = 0; c < 64; c++) mloc = fmaxf(mloc, SC[t * 65 + c]);
            float mold = Mx[t];
            float mnew = fmaxf(mold, mloc);
            float al = __expf(mold - mnew);
            float rs = 0.f;
            for (int c = 0; c < 64; c++) {
                float p = __expf(SC[t * 65 + c] - mnew);
                SC[t * 65 + c] = p;
                rs += p;
            }
            Lw[t] = Lw[t] * al + rs;
            Mx[t] = mnew;
            Al[t] = al;
        }
        // load V block (K no longer needed)
#pragma unroll
        for (int i = 0; i < 8; i++) {
            int li = t + i * 256;
            int r = li >> 5, c = (li & 31) << 2;
            float4 a = *(const float4*)(g_v + (size_t)(ki * 64 + r) * (NKV * DH) + kvh * DH + c);
            float* dp = &KVs[r * 129 + c];
            dp[0] = a.x; dp[1] = a.y; dp[2] = a.z; dp[3] = a.w;
        }
        __syncthreads();
        // O accumulation: thread owns query qq, dims {ao + 4j}
        float al = Al[qq];
#pragma unroll
        for (int j = 0; j < 32; j++) o[j] *= al;
        for (int c = 0; c < 64; c++) {
            float p = SC[qq * 65 + c];
            const float* vr = &KVs[c * 129 + ao];
#pragma unroll
            for (int j = 0; j < 32; j++) o[j] = fmaf(p, vr[4 * j], o[j]);
        }
    }
    __syncthreads();
    float inv = 1.f / Lw[qq];
    float* op = g_att + (size_t)(qb * 64 + qq) * HID + h * DH + ao;
#pragma unroll
    for (int j = 0; j < 32; j++) op[4 * j] = o[j] * inv;
}

// ---------------- launch ----------------
extern "C" void kernel_launch(void* const* d_in, const int* in_sizes, int n_in,
                              void* d_out, int out_size) {
    const float* hid = (const float*)d_in[0];
    const int*   pos = (const int*)d_in[1];
    const float* Wq  = (const float*)d_in[2];
    const float* Wk  = (const float*)d_in[3];
    const float* Wv  = (const float*)d_in[4];
    const float* Wo  = (const float*)d_in[5];
    const float* H   = (const float*)d_in[6];
    float* out = (float*)d_out;

    float *qp, *kp, *vp, *attp, *sqp, *skp;
    cudaGetSymbolAddress((void**)&qp,  g_q);
    cudaGetSymbolAddress((void**)&kp,  g_k);
    cudaGetSymbolAddress((void**)&vp,  g_v);
    cudaGetSymbolAddress((void**)&attp, g_att);
    cudaGetSymbolAddress((void**)&sqp, g_sq);
    cudaGetSymbolAddress((void**)&skp, g_sk);

    const int ATTN_SMEM = (64 * 129 * 2 + 64 * 65 + 192) * sizeof(float);
    cudaFuncSetAttribute(attn_kernel, cudaFuncAttributeMaxDynamicSharedMemorySize, ATTN_SMEM);

    // QKV projections
    gemm_kernel<<<dim3(HID / 128, S_LEN / 128), 256>>>(hid, Wq, qp, S_LEN, HID, HID);
    gemm_kernel<<<dim3((NKV * DH) / 128, S_LEN / 128), 256>>>(hid, Wk, kp, S_LEN, NKV * DH, HID);
    gemm_kernel<<<dim3((NKV * DH) / 128, S_LEN / 128), 256>>>(hid, Wv, vp, S_LEN, NKV * DH, HID);

    // RoPE
    cs_kernel<<<(S_LEN * 64 + 255) / 256, 256>>>(pos);
    rope_kernel<<<(S_LEN * NH * 64 + 255) / 256, 256>>>(qp, NH);
    rope_kernel<<<(S_LEN * NKV * 64 + 255) / 256, 256>>>(kp, NKV);

    // sketches + top-k
    sketch_kernel<<<dim3(NBLK, NH), 128>>>(qp, H, sqp, NH);
    sketch_kernel<<<dim3(NBLK, NKV), 128>>>(kp, H, skp, NKV);
    topk_kernel<<<dim3(NBLK, NH), 64>>>();

    // block-sparse attention
    attn_kernel<<<dim3(NBLK, NH), 256, ATTN_SMEM>>>();

    // output projection
    gemm_kernel<<<dim3(HID / 128, S_LEN / 128), 256>>>(attp, Wo, out, S_LEN, HID, HID);
}

// round 4
// speedup vs baseline: 1.0688x; 1.0688x over previous
#include <cuda_runtime.h>
#include <cuda_bf16.h>
#include <math.h>
#include <stdint.h>

#define S_LEN 4096
#define HID 2048
#define NH 16
#define NKV 4
#define DH 128
#define BLK 64
#define MSK 32
#define KTOP 8
#define NBLK 64   // S_LEN / BLK

typedef __nv_bfloat16 bf16;

// ---------------- scratch (static device allocations; no cudaMalloc) ----------------
__device__ float g_q[S_LEN * NH * DH];
__device__ float g_k[S_LEN * NKV * DH];
__device__ float g_v[S_LEN * NKV * DH];
__device__ float g_att[S_LEN * NH * DH];
__device__ float g_sq[NH * NBLK * MSK];
__device__ float g_sk[NKV * NBLK * MSK];
__device__ int   g_idx[NH * NBLK * KTOP];
__device__ float2 g_cs[S_LEN * 64];

// bf16 hi/lo split buffers
__device__ bf16 g_ahi[S_LEN * HID];
__device__ bf16 g_alo[S_LEN * HID];
__device__ bf16 g_wqt_h[HID * HID];
__device__ bf16 g_wqt_l[HID * HID];
__device__ bf16 g_wkt_h[(NKV * DH) * HID];
__device__ bf16 g_wkt_l[(NKV * DH) * HID];
__device__ bf16 g_wvt_h[(NKV * DH) * HID];
__device__ bf16 g_wvt_l[(NKV * DH) * HID];
__device__ bf16 g_wot_h[HID * HID];
__device__ bf16 g_wot_l[HID * HID];

// ================= helpers =================
__device__ __forceinline__ uint32_t smem_u32(const void* p) {
    uint32_t a;
    asm("{ .reg .u64 t; cvta.to.shared.u64 t, %1; cvt.u32.u64 %0, t; }" : "=r"(a) : "l"(p));
    return a;
}
#define CP_ASYNC16(sa, ga) \
    asm volatile("cp.async.cg.shared.global [%0], [%1], 16;" :: "r"(sa), "l"(ga))
#define CP_COMMIT() asm volatile("cp.async.commit_group;")
#define CP_WAIT0()  asm volatile("cp.async.wait_group 0;")
#define LDSM4(R, A) \
    asm volatile("ldmatrix.sync.aligned.m8n8.x4.shared.b16 {%0,%1,%2,%3}, [%4];" \
                 : "=r"((R)[0]), "=r"((R)[1]), "=r"((R)[2]), "=r"((R)[3]) : "r"(A))
#define MMA16816(D, A, B0, B1) \
    asm volatile("mma.sync.aligned.m16n8k16.row.col.f32.bf16.bf16.f32 " \
                 "{%0,%1,%2,%3}, {%4,%5,%6,%7}, {%8,%9}, {%0,%1,%2,%3};" \
                 : "+f"((D)[0]), "+f"((D)[1]), "+f"((D)[2]), "+f"((D)[3]) \
                 : "r"((A)[0]), "r"((A)[1]), "r"((A)[2]), "r"((A)[3]), "r"(B0), "r"(B1))

// ================= HMMA GEMM: C[M,N] = A[M,K] * Bt[N,K]^T =================
// A, Bt stored as hi/lo bf16 (K contiguous). Tile 128x128, BK=32, double buffered.
#define GH_STRIDE_B 80                       // bytes per SMEM row (40 halves)
#define GH_ARR (128 * GH_STRIDE_B)           // 10240 B per array
#define GH_STAGE (4 * GH_ARR)                // Ah, Al, Bh, Bl
#define GH_SMEM (2 * GH_STAGE)               // 81920 B

__global__ __launch_bounds__(256) void gemm_hmma(const bf16* __restrict__ Ahi,
                                                 const bf16* __restrict__ Alo,
                                                 const bf16* __restrict__ Bhi,
                                                 const bf16* __restrict__ Blo,
                                                 float* __restrict__ C,
                                                 int M, int N, int K) {
    extern __shared__ char smembuf[];
    const uint32_t sbase = smem_u32(smembuf);
    const int t = threadIdx.x;
    const int L = t & 31, wid = t >> 5;
    const int wm = wid >> 2, wn = wid & 3;           // warp grid 2 (m) x 4 (n)
    const int bm = blockIdx.y * 128, bn = blockIdx.x * 128;
    const int NC = K >> 5;                            // BK = 32

    float acc[16][4];
#pragma unroll
    for (int i = 0; i < 16; i++)
#pragma unroll
        for (int j = 0; j < 4; j++) acc[i][j] = 0.f;

    // per-chunk loader: 512 16B ops per array / 256 threads = 2 each
#define GH_LOAD(cc, s) do {                                                   \
        int kc_ = (cc) << 5;                                                  \
        uint32_t st_ = sbase + (s) * GH_STAGE;                                \
        _Pragma("unroll")                                                     \
        for (int i_ = 0; i_ < 2; i_++) {                                      \
            int idx_ = t + i_ * 256;                                          \
            int r_ = idx_ >> 2, ch_ = idx_ & 3;                               \
            uint32_t sw_ = r_ * GH_STRIDE_B + ch_ * 16;                       \
            size_t ga_ = (size_t)(bm + r_) * K + kc_ + ch_ * 8;               \
            size_t gb_ = (size_t)(bn + r_) * K + kc_ + ch_ * 8;               \
            CP_ASYNC16(st_ + sw_,              Ahi + ga_);                    \
            CP_ASYNC16(st_ + GH_ARR + sw_,     Alo + ga_);                    \
            CP_ASYNC16(st_ + 2 * GH_ARR + sw_, Bhi + gb_);                    \
            CP_ASYNC16(st_ + 3 * GH_ARR + sw_, Blo + gb_);                    \
        }                                                                     \
        CP_COMMIT();                                                          \
    } while (0)

    GH_LOAD(0, 0);

    // ldmatrix lane address templates (byte offsets within an array)
    const uint32_t a_lane = (uint32_t)((wm * 64 + (L & 7) + ((L >> 3) & 1) * 8) * GH_STRIDE_B
                                       + ((L >> 4) & 1) * 16);
    const uint32_t b_lane = (uint32_t)((wn * 32 + (L & 7) + ((L >> 4) & 1) * 8) * GH_STRIDE_B
                                       + ((L >> 3) & 1) * 16);

    for (int c = 0; c < NC; c++) {
        CP_WAIT0();
        __syncthreads();
        if (c + 1 < NC) GH_LOAD(c + 1, (c + 1) & 1);

        uint32_t st = sbase + (c & 1) * GH_STAGE;
#pragma unroll
        for (int ks = 0; ks < 2; ks++) {
            uint32_t kb = ks * 32;  // 16 halves
            uint32_t ah[4][4], al[4][4], bh[2][4], bl[2][4];
#pragma unroll
            for (int mi = 0; mi < 4; mi++) {
                uint32_t ad = st + a_lane + mi * 16 * GH_STRIDE_B + kb;
                LDSM4(ah[mi], ad);
                LDSM4(al[mi], ad + GH_ARR);
            }
#pragma unroll
            for (int bi = 0; bi < 2; bi++) {
                uint32_t bd = st + 2 * GH_ARR + b_lane + bi * 16 * GH_STRIDE_B + kb;
                LDSM4(bh[bi], bd);
                LDSM4(bl[bi], bd + GH_ARR);
            }
#pragma unroll
            for (int mi = 0; mi < 4; mi++)
#pragma unroll
                for (int ni = 0; ni < 4; ni++) {
                    float* d = acc[mi * 4 + ni];
                    int bi = ni >> 1, sub = (ni & 1) * 2;
                    MMA16816(d, ah[mi], bh[bi][sub], bh[bi][sub + 1]);
                    MMA16816(d, ah[mi], bl[bi][sub], bl[bi][sub + 1]);
                    MMA16816(d, al[mi], bh[bi][sub], bh[bi][sub + 1]);
                }
        }
        __syncthreads();
    }

    // epilogue: direct float2 stores
#pragma unroll
    for (int mi = 0; mi < 4; mi++)
#pragma unroll
        for (int ni = 0; ni < 4; ni++) {
            float* d = acc[mi * 4 + ni];
            int row = bm + wm * 64 + mi * 16 + (L >> 2);
            int col = bn + wn * 32 + ni * 8 + (L & 3) * 2;
            *(float2*)(C + (size_t)row * N + col) = make_float2(d[0], d[1]);
            *(float2*)(C + (size_t)(row + 8) * N + col) = make_float2(d[2], d[3]);
        }
}

// ---------------- fp32 -> bf16 hi/lo split ----------------
__global__ void split_kernel(const float* __restrict__ x, bf16* __restrict__ hi,
                             bf16* __restrict__ lo, int n4) {
    int i = blockIdx.x * 256 + threadIdx.x;
    if (i >= n4) return;
    float4 v = ((const float4*)x)[i];
    float vv[4] = {v.x, v.y, v.z, v.w};
    bf16 h[4], l[4];
#pragma unroll
    for (int j = 0; j < 4; j++) {
        h[j] = __float2bfloat16(vv[j]);
        l[j] = __float2bfloat16(vv[j] - __bfloat162float(h[j]));
    }
    *(uint2*)(hi + 4 * (size_t)i) = *(uint2*)h;
    *(uint2*)(lo + 4 * (size_t)i) = *(uint2*)l;
}

// ---------------- W[K,N] -> Bt[N,K] transpose + hi/lo split ----------------
__global__ void tsplit_kernel(const float* __restrict__ W, bf16* __restrict__ hi,
                              bf16* __restrict__ lo, int K, int N) {
    __shared__ float tile[32][33];
    int kb = blockIdx.y * 32, nb = blockIdx.x * 32;
    int tx = threadIdx.x, ty = threadIdx.y;  // 32 x 8
#pragma unroll
    for (int i = 0; i < 32; i += 8)
        tile[ty + i][tx] = W[(size_t)(kb + ty + i) * N + nb + tx];
    __syncthreads();
#pragma unroll
    for (int i = 0; i < 32; i += 8) {
        float v = tile[tx][ty + i];
        size_t o = (size_t)(nb + ty + i) * K + kb + tx;
        bf16 h = __float2bfloat16(v);
        hi[o] = h;
        lo[o] = __float2bfloat16(v - __bfloat162float(h));
    }
}

// ---------------- cos/sin table ----------------
__global__ void cs_kernel(const int* __restrict__ pos_ids) {
    int idx = blockIdx.x * 256 + threadIdx.x;
    if (idx >= S_LEN * 64) return;
    int s = idx >> 6, i = idx & 63;
    double inv = exp((double)i * -0.14391156831212753);  // -ln(10000)/64
    double f = (double)pos_ids[s] * inv;
    const double TWO_PI = 6.283185307179586476925287;
    double fr = f - TWO_PI * floor(f * 0.15915494309189534561);
    g_cs[idx] = make_float2(cosf((float)fr), sinf((float)fr));
}

// ---------------- RoPE (in place) ----------------
__global__ void rope_kernel(float* __restrict__ x, int nheads) {
    int idx = blockIdx.x * 256 + threadIdx.x;
    int total = S_LEN * nheads * 64;
    if (idx >= total) return;
    int i = idx & 63;
    int h = (idx >> 6) % nheads;
    int s = idx / (64 * nheads);
    float2 cs = g_cs[s * 64 + i];
    float* p = x + (size_t)s * nheads * DH + h * DH;
    float x1 = p[i], x2 = p[i + 64];
    p[i]      = x1 * cs.x - x2 * cs.y;
    p[i + 64] = x2 * cs.x + x1 * cs.y;
}

// ---------------- sketch ----------------
__global__ void sketch_kernel(const float* __restrict__ x, const float* __restrict__ H,
                              float* __restrict__ dst, int nheads) {
    int blk = blockIdx.x, h = blockIdx.y;
    int t = threadIdx.x;  // 128
    __shared__ float xb[128];
    int stride = nheads * DH;
    const float* base = x + (size_t)blk * BLK * stride + h * DH + t;
    float s = 0.f;
    for (int r = 0; r < BLK; r++) s += base[(size_t)r * stride];
    xb[t] = s * (1.f / 64.f);
    __syncthreads();
    if (t < MSK) {
        float a = 0.f;
        for (int d = 0; d < DH; d++) a += xb[d] * H[d * MSK + t];
        dst[((size_t)h * NBLK + blk) * MSK + t] = a;
    }
}

// ---------------- top-k ----------------
__global__ void topk_kernel() {
    int qb = blockIdx.x, h = blockIdx.y;
    int j = threadIdx.x;  // 0..63
    __shared__ float sc[64];
    float s;
    if (j > qb) {
        s = -1e9f;
    } else {
        const float* a = g_sq + ((size_t)h * NBLK + qb) * MSK;
        const float* b = g_sk + ((size_t)(h >> 2) * NBLK + j) * MSK;
        s = 0.f;
        for (int m = 0; m < MSK; m++) s += a[m] * b[m];
    }
    if (j == qb) s = 1e9f;
    sc[j] = s;
    __syncthreads();
    if (j == 0) {
        for (int tsel = 0; tsel < KTOP; tsel++) {
            float best = -3.4e38f;
            int bi = 0;
            for (int jj = 0; jj < 64; jj++)
                if (sc[jj] > best) { best = sc[jj]; bi = jj; }
            g_idx[((size_t)h * NBLK + qb) * KTOP + tsel] = bi;
            sc[bi] = -3.4e38f;
        }
    }
}

// ---------------- block-sparse flash attention ----------------
__global__ __launch_bounds__(256) void attn_kernel() {
    extern __shared__ float sm[];
    float* Qs  = sm;
    float* KVs = Qs + 64 * 129;
    float* SC  = KVs + 64 * 129;
    float* Mx  = SC + 64 * 65;
    float* Lw  = Mx + 64;
    float* Al  = Lw + 64;

    const int qb = blockIdx.x, h = blockIdx.y, kvh = h >> 2;
    const int t = threadIdx.x;
    const float scale = 0.08838834764831845f;

#pragma unroll
    for (int i = 0; i < 8; i++) {
        int li = t + i * 256;
        int r = li >> 5, c = (li & 31) << 2;
        float4 a = *(const float4*)(g_q + (size_t)(qb * 64 + r) * HID + h * DH + c);
        float* dp = &Qs[r * 129 + c];
        dp[0] = a.x; dp[1] = a.y; dp[2] = a.z; dp[3] = a.w;
    }
    if (t < 64) { Mx[t] = -3.4e38f; Lw[t] = 0.f; }

    float o[32];
#pragma unroll
    for (int j = 0; j < 32; j++) o[j] = 0.f;

    const int q0 = (t >> 4) << 2;
    const int k0 = (t & 15) << 2;
    const int qq = t >> 2;
    const int ao = t & 3;

    for (int it = 0; it < KTOP; it++) {
        int ki = g_idx[((size_t)h * NBLK + qb) * KTOP + it];
        __syncthreads();
#pragma unroll
        for (int i = 0; i < 8; i++) {
            int li = t + i * 256;
            int r = li >> 5, c = (li & 31) << 2;
            float4 a = *(const float4*)(g_k + (size_t)(ki * 64 + r) * (NKV * DH) + kvh * DH + c);
            float* dp = &KVs[r * 129 + c];
            dp[0] = a.x; dp[1] = a.y; dp[2] = a.z; dp[3] = a.w;
        }
        __syncthreads();
        float acc[4][4];
#pragma unroll
        for (int i = 0; i < 4; i++)
#pragma unroll
            for (int j = 0; j < 4; j++) acc[i][j] = 0.f;
        for (int d = 0; d < DH; d++) {
            float qv[4], kv[4];
#pragma unroll
            for (int i = 0; i < 4; i++) qv[i] = Qs[(q0 + i) * 129 + d];
#pragma unroll
            for (int j = 0; j < 4; j++) kv[j] = KVs[(k0 + j) * 129 + d];
#pragma unroll
            for (int i = 0; i < 4; i++)
#pragma unroll
                for (int j = 0; j < 4; j++) acc[i][j] = fmaf(qv[i], kv[j], acc[i][j]);
        }
        const int kbase = ki * 64, qbase = qb * 64;
#pragma unroll
        for (int i = 0; i < 4; i++)
#pragma unroll
            for (int j = 0; j < 4; j++) {
                float val = (kbase + k0 + j <= qbase + q0 + i) ? acc[i][j] * scale : -1e9f;
                SC[(q0 + i) * 65 + k0 + j] = val;
            }
        __syncthreads();
        if (t < 64) {
            float mloc = -3.4e38f;
            for (int c = 0; c < 64; c++) mloc = fmaxf(mloc, SC[t * 65 + c]);
            float mold = Mx[t];
            float mnew = fmaxf(mold, mloc);
            float al = __expf(mold - mnew);
            float rs = 0.f;
            for (int c = 0; c < 64; c++) {
                float p = __expf(SC[t * 65 + c] - mnew);
                SC[t * 65 + c] = p;
                rs += p;
            }
            Lw[t] = Lw[t] * al + rs;
            Mx[t] = mnew;
            Al[t] = al;
        }
#pragma unroll
        for (int i = 0; i < 8; i++) {
            int li = t + i * 256;
            int r = li >> 5, c = (li & 31) << 2;
            float4 a = *(const float4*)(g_v + (size_t)(ki * 64 + r) * (NKV * DH) + kvh * DH + c);
            float* dp = &KVs[r * 129 + c];
            dp[0] = a.x; dp[1] = a.y; dp[2] = a.z; dp[3] = a.w;
        }
        __syncthreads();
        float al = Al[qq];
#pragma unroll
        for (int j = 0; j < 32; j++) o[j] *= al;
        for (int c = 0; c < 64; c++) {
            float p = SC[qq * 65 + c];
            const float* vr = &KVs[c * 129 + ao];
#pragma unroll
            for (int j = 0; j < 32; j++) o[j] = fmaf(p, vr[4 * j], o[j]);
        }
    }
    __syncthreads();
    float inv = 1.f / Lw[qq];
    float* op = g_att + (size_t)(qb * 64 + qq) * HID + h * DH + ao;
#pragma unroll
    for (int j = 0; j < 32; j++) op[4 * j] = o[j] * inv;
}

// ---------------- launch ----------------
extern "C" void kernel_launch(void* const* d_in, const int* in_sizes, int n_in,
                              void* d_out, int out_size) {
    const float* hid = (const float*)d_in[0];
    const int*   pos = (const int*)d_in[1];
    const float* Wq  = (const float*)d_in[2];
    const float* Wk  = (const float*)d_in[3];
    const float* Wv  = (const float*)d_in[4];
    const float* Wo  = (const float*)d_in[5];
    const float* H   = (const float*)d_in[6];
    float* out = (float*)d_out;

    float *qp, *kp, *vp, *attp, *sqp, *skp;
    bf16 *ahi, *alo, *wqh, *wql, *wkh, *wkl, *wvh, *wvl, *woh, *wol;
    cudaGetSymbolAddress((void**)&qp,   g_q);
    cudaGetSymbolAddress((void**)&kp,   g_k);
    cudaGetSymbolAddress((void**)&vp,   g_v);
    cudaGetSymbolAddress((void**)&attp, g_att);
    cudaGetSymbolAddress((void**)&sqp,  g_sq);
    cudaGetSymbolAddress((void**)&skp,  g_sk);
    cudaGetSymbolAddress((void**)&ahi,  g_ahi);
    cudaGetSymbolAddress((void**)&alo,  g_alo);
    cudaGetSymbolAddress((void**)&wqh,  g_wqt_h);
    cudaGetSymbolAddress((void**)&wql,  g_wqt_l);
    cudaGetSymbolAddress((void**)&wkh,  g_wkt_h);
    cudaGetSymbolAddress((void**)&wkl,  g_wkt_l);
    cudaGetSymbolAddress((void**)&wvh,  g_wvt_h);
    cudaGetSymbolAddress((void**)&wvl,  g_wvt_l);
    cudaGetSymbolAddress((void**)&woh,  g_wot_h);
    cudaGetSymbolAddress((void**)&wol,  g_wot_l);

    const int ATTN_SMEM = (64 * 129 * 2 + 64 * 65 + 192) * sizeof(float);
    cudaFuncSetAttribute(attn_kernel, cudaFuncAttributeMaxDynamicSharedMemorySize, ATTN_SMEM);
    cudaFuncSetAttribute(gemm_hmma, cudaFuncAttributeMaxDynamicSharedMemorySize, GH_SMEM);

    dim3 tb(32, 8);
    // weight transposes + splits
    tsplit_kernel<<<dim3(HID / 32, HID / 32), tb>>>(Wq, wqh, wql, HID, HID);
    tsplit_kernel<<<dim3((NKV * DH) / 32, HID / 32), tb>>>(Wk, wkh, wkl, HID, NKV * DH);
    tsplit_kernel<<<dim3((NKV * DH) / 32, HID / 32), tb>>>(Wv, wvh, wvl, HID, NKV * DH);
    tsplit_kernel<<<dim3(HID / 32, HID / 32), tb>>>(Wo, woh, wol, HID, HID);
    // hidden split
    split_kernel<<<(S_LEN * HID / 4 + 255) / 256, 256>>>(hid, ahi, alo, S_LEN * HID / 4);

    // QKV projections (HMMA tensor cores)
    gemm_hmma<<<dim3(HID / 128, S_LEN / 128), 256, GH_SMEM>>>(ahi, alo, wqh, wql, qp, S_LEN, HID, HID);
    gemm_hmma<<<dim3((NKV * DH) / 128, S_LEN / 128), 256, GH_SMEM>>>(ahi, alo, wkh, wkl, kp, S_LEN, NKV * DH, HID);
    gemm_hmma<<<dim3((NKV * DH) / 128, S_LEN / 128), 256, GH_SMEM>>>(ahi, alo, wvh, wvl, vp, S_LEN, NKV * DH, HID);

    // RoPE
    cs_kernel<<<(S_LEN * 64 + 255) / 256, 256>>>(pos);
    rope_kernel<<<(S_LEN * NH * 64 + 255) / 256, 256>>>(qp, NH);
    rope_kernel<<<(S_LEN * NKV * 64 + 255) / 256, 256>>>(kp, NKV);

    // sketches + top-k
    sketch_kernel<<<dim3(NBLK, NH), 128>>>(qp, H, sqp, NH);
    sketch_kernel<<<dim3(NBLK, NKV), 128>>>(kp, H, skp, NKV);
    topk_kernel<<<dim3(NBLK, NH), 64>>>();

    // block-sparse attention
    attn_kernel<<<dim3(NBLK, NH), 256, ATTN_SMEM>>>();

    // output projection (HMMA)
    split_kernel<<<(S_LEN * HID / 4 + 255) / 256, 256>>>(attp, ahi, alo, S_LEN * HID / 4);
    gemm_hmma<<<dim3(HID / 128, S_LEN / 128), 256, GH_SMEM>>>(ahi, alo, woh, wol, out, S_LEN, HID, HID);
}

// round 5
// speedup vs baseline: 1.6828x; 1.5745x over previous
#include <cuda_runtime.h>
#include <cuda_bf16.h>
#include <math.h>
#include <stdint.h>

#define S_LEN 4096
#define HID 2048
#define NH 16
#define NKV 4
#define DH 128
#define BLK 64
#define MSK 32
#define KTOP 8
#define NBLK 64   // S_LEN / BLK

typedef __nv_bfloat16 bf16;

// ---------------- scratch (static device allocations; no cudaMalloc) ----------------
__device__ float g_q[S_LEN * NH * DH];
__device__ float g_k[S_LEN * NKV * DH];
__device__ float g_v[S_LEN * NKV * DH];
__device__ float g_sq[NH * NBLK * MSK];
__device__ float g_sk[NKV * NBLK * MSK];
__device__ int   g_idx[NH * NBLK * KTOP];
__device__ float2 g_cs[S_LEN * 64];

// bf16 hi/lo split buffers
__device__ bf16 g_ahi[S_LEN * HID];
__device__ bf16 g_alo[S_LEN * HID];
__device__ bf16 g_bhi[S_LEN * HID];   // attention output hi
__device__ bf16 g_blo[S_LEN * HID];   // attention output lo
__device__ bf16 g_wqt_h[HID * HID];
__device__ bf16 g_wqt_l[HID * HID];
__device__ bf16 g_wkt_h[(NKV * DH) * HID];
__device__ bf16 g_wkt_l[(NKV * DH) * HID];
__device__ bf16 g_wvt_h[(NKV * DH) * HID];
__device__ bf16 g_wvt_l[(NKV * DH) * HID];
__device__ bf16 g_wot_h[HID * HID];
__device__ bf16 g_wot_l[HID * HID];

// ================= helpers =================
__device__ __forceinline__ uint32_t smem_u32(const void* p) {
    uint32_t a;
    asm("{ .reg .u64 t; cvta.to.shared.u64 t, %1; cvt.u32.u64 %0, t; }" : "=r"(a) : "l"(p));
    return a;
}
#define CP_ASYNC16(sa, ga) \
    asm volatile("cp.async.cg.shared.global [%0], [%1], 16;" :: "r"(sa), "l"(ga))
#define CP_COMMIT() asm volatile("cp.async.commit_group;")
#define CP_WAIT(n)  asm volatile("cp.async.wait_group %0;" :: "n"(n))
#define LDSM4(R, A) \
    asm volatile("ldmatrix.sync.aligned.m8n8.x4.shared.b16 {%0,%1,%2,%3}, [%4];" \
                 : "=r"((R)[0]), "=r"((R)[1]), "=r"((R)[2]), "=r"((R)[3]) : "r"(A))
#define MMA16816(D, A, B0, B1) \
    asm volatile("mma.sync.aligned.m16n8k16.row.col.f32.bf16.bf16.f32 " \
                 "{%0,%1,%2,%3}, {%4,%5,%6,%7}, {%8,%9}, {%0,%1,%2,%3};" \
                 : "+f"((D)[0]), "+f"((D)[1]), "+f"((D)[2]), "+f"((D)[3]) \
                 : "r"((A)[0]), "r"((A)[1]), "r"((A)[2]), "r"((A)[3]), "r"(B0), "r"(B1))

// ================= HMMA GEMM: C[M,N] = A[M,K] * Bt[N,K]^T =================
// A, Bt stored as hi/lo bf16 (K contiguous). Tile 128x128, BK=32, 4-stage cp.async.
#define GH_STRIDE_B 80                       // bytes per SMEM row (40 halves)
#define GH_ARR (128 * GH_STRIDE_B)           // 10240 B per array
#define GH_STAGE (4 * GH_ARR)                // Ah, Al, Bh, Bl  = 40960 B
#define GH_STAGES 4
#define GH_SMEM (GH_STAGES * GH_STAGE)       // 163840 B

__global__ __launch_bounds__(256) void gemm_hmma(const bf16* __restrict__ Ahi,
                                                 const bf16* __restrict__ Alo,
                                                 const bf16* __restrict__ Bhi,
                                                 const bf16* __restrict__ Blo,
                                                 float* __restrict__ C,
                                                 int M, int N, int K) {
    extern __shared__ char smembuf[];
    const uint32_t sbase = smem_u32(smembuf);
    const int t = threadIdx.x;
    const int L = t & 31, wid = t >> 5;
    const int wm = wid >> 2, wn = wid & 3;           // warp grid 2 (m) x 4 (n)
    const int bm = blockIdx.y * 128, bn = blockIdx.x * 128;
    const int NC = K >> 5;                            // BK = 32

    float acc[16][4];
#pragma unroll
    for (int i = 0; i < 16; i++)
#pragma unroll
        for (int j = 0; j < 4; j++) acc[i][j] = 0.f;

#define GH_LOAD(cc, s) do {                                                   \
        int kc_ = (cc) << 5;                                                  \
        uint32_t st_ = sbase + (s) * GH_STAGE;                                \
        _Pragma("unroll")                                                     \
        for (int i_ = 0; i_ < 2; i_++) {                                      \
            int idx_ = t + i_ * 256;                                          \
            int r_ = idx_ >> 2, ch_ = idx_ & 3;                               \
            uint32_t sw_ = r_ * GH_STRIDE_B + ch_ * 16;                       \
            size_t ga_ = (size_t)(bm + r_) * K + kc_ + ch_ * 8;               \
            size_t gb_ = (size_t)(bn + r_) * K + kc_ + ch_ * 8;               \
            CP_ASYNC16(st_ + sw_,              Ahi + ga_);                    \
            CP_ASYNC16(st_ + GH_ARR + sw_,     Alo + ga_);                    \
            CP_ASYNC16(st_ + 2 * GH_ARR + sw_, Bhi + gb_);                    \
            CP_ASYNC16(st_ + 3 * GH_ARR + sw_, Blo + gb_);                    \
        }                                                                     \
        CP_COMMIT();                                                          \
    } while (0)

    // prologue: fill 3 of 4 stages
    GH_LOAD(0, 0);
    GH_LOAD(1, 1);
    GH_LOAD(2, 2);

    const uint32_t a_lane = (uint32_t)((wm * 64 + (L & 7) + ((L >> 3) & 1) * 8) * GH_STRIDE_B
                                       + ((L >> 4) & 1) * 16);
    const uint32_t b_lane = (uint32_t)((wn * 32 + (L & 7) + ((L >> 4) & 1) * 8) * GH_STRIDE_B
                                       + ((L >> 3) & 1) * 16);

    for (int c = 0; c < NC; c++) {
        // ensure group c complete (tail-aware), then make all threads' copies visible
        if (c + 3 < NC)      { CP_WAIT(2); }
        else if (c + 2 < NC) { CP_WAIT(2); }   // c == NC-3: groups c+1,c+2 pending
        else if (c + 1 < NC) { CP_WAIT(1); }   // c == NC-2
        else                 { CP_WAIT(0); }   // c == NC-1
        __syncthreads();
        // prefetch chunk c+3 into stage (c+3)&3 == (c-1)&3 (freed by the barrier above)
        if (c + 3 < NC) GH_LOAD(c + 3, (c + 3) & 3);

        uint32_t st = sbase + (c & 3) * GH_STAGE;
#pragma unroll
        for (int ks = 0; ks < 2; ks++) {
            uint32_t kb = ks * 32;  // 16 halves
            uint32_t ah[4][4], al[4][4], bh[2][4], bl[2][4];
#pragma unroll
            for (int mi = 0; mi < 4; mi++) {
                uint32_t ad = st + a_lane + mi * 16 * GH_STRIDE_B + kb;
                LDSM4(ah[mi], ad);
                LDSM4(al[mi], ad + GH_ARR);
            }
#pragma unroll
            for (int bi = 0; bi < 2; bi++) {
                uint32_t bd = st + 2 * GH_ARR + b_lane + bi * 16 * GH_STRIDE_B + kb;
                LDSM4(bh[bi], bd);
                LDSM4(bl[bi], bd + GH_ARR);
            }
#pragma unroll
            for (int mi = 0; mi < 4; mi++)
#pragma unroll
                for (int ni = 0; ni < 4; ni++) {
                    float* d = acc[mi * 4 + ni];
                    int bi = ni >> 1, sub = (ni & 1) * 2;
                    MMA16816(d, ah[mi], bh[bi][sub], bh[bi][sub + 1]);
                    MMA16816(d, ah[mi], bl[bi][sub], bl[bi][sub + 1]);
                    MMA16816(d, al[mi], bh[bi][sub], bh[bi][sub + 1]);
                }
        }
    }

    // epilogue: direct float2 stores
#pragma unroll
    for (int mi = 0; mi < 4; mi++)
#pragma unroll
        for (int ni = 0; ni < 4; ni++) {
            float* d = acc[mi * 4 + ni];
            int row = bm + wm * 64 + mi * 16 + (L >> 2);
            int col = bn + wn * 32 + ni * 8 + (L & 3) * 2;
            *(float2*)(C + (size_t)row * N + col) = make_float2(d[0], d[1]);
            *(float2*)(C + (size_t)(row + 8) * N + col) = make_float2(d[2], d[3]);
        }
}

// ---------------- fp32 -> bf16 hi/lo split ----------------
__global__ void split_kernel(const float* __restrict__ x, bf16* __restrict__ hi,
                             bf16* __restrict__ lo, int n4) {
    int i = blockIdx.x * 256 + threadIdx.x;
    if (i >= n4) return;
    float4 v = ((const float4*)x)[i];
    float vv[4] = {v.x, v.y, v.z, v.w};
    bf16 h[4], l[4];
#pragma unroll
    for (int j = 0; j < 4; j++) {
        h[j] = __float2bfloat16(vv[j]);
        l[j] = __float2bfloat16(vv[j] - __bfloat162float(h[j]));
    }
    *(uint2*)(hi + 4 * (size_t)i) = *(uint2*)h;
    *(uint2*)(lo + 4 * (size_t)i) = *(uint2*)l;
}

// ---------------- W[K,N] -> Bt[N,K] transpose + hi/lo split ----------------
__global__ void tsplit_kernel(const float* __restrict__ W, bf16* __restrict__ hi,
                              bf16* __restrict__ lo, int K, int N) {
    __shared__ float tile[32][33];
    int kb = blockIdx.y * 32, nb = blockIdx.x * 32;
    int tx = threadIdx.x, ty = threadIdx.y;  // 32 x 8
#pragma unroll
    for (int i = 0; i < 32; i += 8)
        tile[ty + i][tx] = W[(size_t)(kb + ty + i) * N + nb + tx];
    __syncthreads();
#pragma unroll
    for (int i = 0; i < 32; i += 8) {
        float v = tile[tx][ty + i];
        size_t o = (size_t)(nb + ty + i) * K + kb + tx;
        bf16 h = __float2bfloat16(v);
        hi[o] = h;
        lo[o] = __float2bfloat16(v - __bfloat162float(h));
    }
}

// ---------------- cos/sin table ----------------
__global__ void cs_kernel(const int* __restrict__ pos_ids) {
    int idx = blockIdx.x * 256 + threadIdx.x;
    if (idx >= S_LEN * 64) return;
    int s = idx >> 6, i = idx & 63;
    double inv = exp((double)i * -0.14391156831212753);  // -ln(10000)/64
    double f = (double)pos_ids[s] * inv;
    const double TWO_PI = 6.283185307179586476925287;
    double fr = f - TWO_PI * floor(f * 0.15915494309189534561);
    g_cs[idx] = make_float2(cosf((float)fr), sinf((float)fr));
}

// ---------------- RoPE (in place) ----------------
__global__ void rope_kernel(float* __restrict__ x, int nheads) {
    int idx = blockIdx.x * 256 + threadIdx.x;
    int total = S_LEN * nheads * 64;
    if (idx >= total) return;
    int i = idx & 63;
    int h = (idx >> 6) % nheads;
    int s = idx / (64 * nheads);
    float2 cs = g_cs[s * 64 + i];
    float* p = x + (size_t)s * nheads * DH + h * DH;
    float x1 = p[i], x2 = p[i + 64];
    p[i]      = x1 * cs.x - x2 * cs.y;
    p[i + 64] = x2 * cs.x + x1 * cs.y;
}

// ---------------- sketch ----------------
__global__ void sketch_kernel(const float* __restrict__ x, const float* __restrict__ H,
                              float* __restrict__ dst, int nheads) {
    int blk = blockIdx.x, h = blockIdx.y;
    int t = threadIdx.x;  // 128
    __shared__ float xb[128];
    int stride = nheads * DH;
    const float* base = x + (size_t)blk * BLK * stride + h * DH + t;
    float s = 0.f;
    for (int r = 0; r < BLK; r++) s += base[(size_t)r * stride];
    xb[t] = s * (1.f / 64.f);
    __syncthreads();
    if (t < MSK) {
        float a = 0.f;
        for (int d = 0; d < DH; d++) a += xb[d] * H[d * MSK + t];
        dst[((size_t)h * NBLK + blk) * MSK + t] = a;
    }
}

// ---------------- top-k ----------------
__global__ void topk_kernel() {
    int qb = blockIdx.x, h = blockIdx.y;
    int j = threadIdx.x;  // 0..63
    __shared__ float sc[64];
    float s;
    if (j > qb) {
        s = -1e9f;
    } else {
        const float* a = g_sq + ((size_t)h * NBLK + qb) * MSK;
        const float* b = g_sk + ((size_t)(h >> 2) * NBLK + j) * MSK;
        s = 0.f;
        for (int m = 0; m < MSK; m++) s += a[m] * b[m];
    }
    if (j == qb) s = 1e9f;
    sc[j] = s;
    __syncthreads();
    if (j == 0) {
        for (int tsel = 0; tsel < KTOP; tsel++) {
            float best = -3.4e38f;
            int bi = 0;
            for (int jj = 0; jj < 64; jj++)
                if (sc[jj] > best) { best = sc[jj]; bi = jj; }
            g_idx[((size_t)h * NBLK + qb) * KTOP + tsel] = bi;
            sc[bi] = -3.4e38f;
        }
    }
}

// ---------------- block-sparse flash attention (writes bf16 hi/lo directly) ----------------
__global__ __launch_bounds__(256) void attn_kernel() {
    extern __shared__ float sm[];
    float* Qs  = sm;
    float* KVs = Qs + 64 * 129;
    float* SC  = KVs + 64 * 129;
    float* Mx  = SC + 64 * 65;
    float* Lw  = Mx + 64;
    float* Al  = Lw + 64;

    const int qb = blockIdx.x, h = blockIdx.y, kvh = h >> 2;
    const int t = threadIdx.x;
    const float scale = 0.08838834764831845f;

#pragma unroll
    for (int i = 0; i < 8; i++) {
        int li = t + i * 256;
        int r = li >> 5, c = (li & 31) << 2;
        float4 a = *(const float4*)(g_q + (size_t)(qb * 64 + r) * HID + h * DH + c);
        float* dp = &Qs[r * 129 + c];
        dp[0] = a.x; dp[1] = a.y; dp[2] = a.z; dp[3] = a.w;
    }
    if (t < 64) { Mx[t] = -3.4e38f; Lw[t] = 0.f; }

    float o[32];
#pragma unroll
    for (int j = 0; j < 32; j++) o[j] = 0.f;

    const int q0 = (t >> 4) << 2;
    const int k0 = (t & 15) << 2;
    const int qq = t >> 2;
    const int ao = t & 3;

    for (int it = 0; it < KTOP; it++) {
        int ki = g_idx[((size_t)h * NBLK + qb) * KTOP + it];
        __syncthreads();
#pragma unroll
        for (int i = 0; i < 8; i++) {
            int li = t + i * 256;
            int r = li >> 5, c = (li & 31) << 2;
            float4 a = *(const float4*)(g_k + (size_t)(ki * 64 + r) * (NKV * DH) + kvh * DH + c);
            float* dp = &KVs[r * 129 + c];
            dp[0] = a.x; dp[1] = a.y; dp[2] = a.z; dp[3] = a.w;
        }
        __syncthreads();
        float acc[4][4];
#pragma unroll
        for (int i = 0; i < 4; i++)
#pragma unroll
            for (int j = 0; j < 4; j++) acc[i][j] = 0.f;
        for (int d = 0; d < DH; d++) {
            float qv[4], kv[4];
#pragma unroll
            for (int i = 0; i < 4; i++) qv[i] = Qs[(q0 + i) * 129 + d];
#pragma unroll
            for (int j = 0; j < 4; j++) kv[j] = KVs[(k0 + j) * 129 + d];
#pragma unroll
            for (int i = 0; i < 4; i++)
#pragma unroll
                for (int j = 0; j < 4; j++) acc[i][j] = fmaf(qv[i], kv[j], acc[i][j]);
        }
        const int kbase = ki * 64, qbase = qb * 64;
#pragma unroll
        for (int i = 0; i < 4; i++)
#pragma unroll
            for (int j = 0; j < 4; j++) {
                float val = (kbase + k0 + j <= qbase + q0 + i) ? acc[i][j] * scale : -1e9f;
                SC[(q0 + i) * 65 + k0 + j] = val;
            }
        __syncthreads();
        if (t < 64) {
            float mloc = -3.4e38f;
            for (int c = 0; c < 64; c++) mloc = fmaxf(mloc, SC[t * 65 + c]);
            float mold = Mx[t];
            float mnew = fmaxf(mold, mloc);
            float al = __expf(mold - mnew);
            float rs = 0.f;
            for (int c = 0; c < 64; c++) {
                float p = __expf(SC[t * 65 + c] - mnew);
                SC[t * 65 + c] = p;
                rs += p;
            }
            Lw[t] = Lw[t] * al + rs;
            Mx[t] = mnew;
            Al[t] = al;
        }
#pragma unroll
        for (int i = 0; i < 8; i++) {
            int li = t + i * 256;
            int r = li >> 5, c = (li & 31) << 2;
            float4 a = *(const float4*)(g_v + (size_t)(ki * 64 + r) * (NKV * DH) + kvh * DH + c);
            float* dp = &KVs[r * 129 + c];
            dp[0] = a.x; dp[1] = a.y; dp[2] = a.z; dp[3] = a.w;
        }
        __syncthreads();
        float al = Al[qq];
#pragma unroll
        for (int j = 0; j < 32; j++) o[j] *= al;
        for (int c = 0; c < 64; c++) {
            float p = SC[qq * 65 + c];
            const float* vr = &KVs[c * 129 + ao];
#pragma unroll
            for (int j = 0; j < 32; j++) o[j] = fmaf(p, vr[4 * j], o[j]);
        }
    }
    __syncthreads();
    float inv = 1.f / Lw[qq];
    size_t obase = (size_t)(qb * 64 + qq) * HID + h * DH + ao;
#pragma unroll
    for (int j = 0; j < 32; j++) {
        float v = o[j] * inv;
        bf16 hh = __float2bfloat16(v);
        g_bhi[obase + 4 * j] = hh;
        g_blo[obase + 4 * j] = __float2bfloat16(v - __bfloat162float(hh));
    }
}

// ---------------- launch ----------------
extern "C" void kernel_launch(void* const* d_in, const int* in_sizes, int n_in,
                              void* d_out, int out_size) {
    const float* hid = (const float*)d_in[0];
    const int*   pos = (const int*)d_in[1];
    const float* Wq  = (const float*)d_in[2];
    const float* Wk  = (const float*)d_in[3];
    const float* Wv  = (const float*)d_in[4];
    const float* Wo  = (const float*)d_in[5];
    const float* H   = (const float*)d_in[6];
    float* out = (float*)d_out;

    float *qp, *kp, *vp, *sqp, *skp;
    bf16 *ahi, *alo, *bhi, *blo, *wqh, *wql, *wkh, *wkl, *wvh, *wvl, *woh, *wol;
    cudaGetSymbolAddress((void**)&qp,   g_q);
    cudaGetSymbolAddress((void**)&kp,   g_k);
    cudaGetSymbolAddress((void**)&vp,   g_v);
    cudaGetSymbolAddress((void**)&sqp,  g_sq);
    cudaGetSymbolAddress((void**)&skp,  g_sk);
    cudaGetSymbolAddress((void**)&ahi,  g_ahi);
    cudaGetSymbolAddress((void**)&alo,  g_alo);
    cudaGetSymbolAddress((void**)&bhi,  g_bhi);
    cudaGetSymbolAddress((void**)&blo,  g_blo);
    cudaGetSymbolAddress((void**)&wqh,  g_wqt_h);
    cudaGetSymbolAddress((void**)&wql,  g_wqt_l);
    cudaGetSymbolAddress((void**)&wkh,  g_wkt_h);
    cudaGetSymbolAddress((void**)&wkl,  g_wkt_l);
    cudaGetSymbolAddress((void**)&wvh,  g_wvt_h);
    cudaGetSymbolAddress((void**)&wvl,  g_wvt_l);
    cudaGetSymbolAddress((void**)&woh,  g_wot_h);
    cudaGetSymbolAddress((void**)&wol,  g_wot_l);

    const int ATTN_SMEM = (64 * 129 * 2 + 64 * 65 + 192) * sizeof(float);
    cudaFuncSetAttribute(attn_kernel, cudaFuncAttributeMaxDynamicSharedMemorySize, ATTN_SMEM);
    cudaFuncSetAttribute(gemm_hmma, cudaFuncAttributeMaxDynamicSharedMemorySize, GH_SMEM);

    dim3 tb(32, 8);
    // weight transposes + splits
    tsplit_kernel<<<dim3(HID / 32, HID / 32), tb>>>(Wq, wqh, wql, HID, HID);
    tsplit_kernel<<<dim3((NKV * DH) / 32, HID / 32), tb>>>(Wk, wkh, wkl, HID, NKV * DH);
    tsplit_kernel<<<dim3((NKV * DH) / 32, HID / 32), tb>>>(Wv, wvh, wvl, HID, NKV * DH);
    tsplit_kernel<<<dim3(HID / 32, HID / 32), tb>>>(Wo, woh, wol, HID, HID);
    // hidden split
    split_kernel<<<(S_LEN * HID / 4 + 255) / 256, 256>>>(hid, ahi, alo, S_LEN * HID / 4);

    // QKV projections (HMMA tensor cores)
    gemm_hmma<<<dim3(HID / 128, S_LEN / 128), 256, GH_SMEM>>>(ahi, alo, wqh, wql, qp, S_LEN, HID, HID);
    gemm_hmma<<<dim3((NKV * DH) / 128, S_LEN / 128), 256, GH_SMEM>>>(ahi, alo, wkh, wkl, kp, S_LEN, NKV * DH, HID);
    gemm_hmma<<<dim3((NKV * DH) / 128, S_LEN / 128), 256, GH_SMEM>>>(ahi, alo, wvh, wvl, vp, S_LEN, NKV * DH, HID);

    // RoPE
    cs_kernel<<<(S_LEN * 64 + 255) / 256, 256>>>(pos);
    rope_kernel<<<(S_LEN * NH * 64 + 255) / 256, 256>>>(qp, NH);
    rope_kernel<<<(S_LEN * NKV * 64 + 255) / 256, 256>>>(kp, NKV);

    // sketches + top-k
    sketch_kernel<<<dim3(NBLK, NH), 128>>>(qp, H, sqp, NH);
    sketch_kernel<<<dim3(NBLK, NKV), 128>>>(kp, H, skp, NKV);
    topk_kernel<<<dim3(NBLK, NH), 64>>>();

    // block-sparse attention (emits bf16 hi/lo directly)
    attn_kernel<<<dim3(NBLK, NH), 256, ATTN_SMEM>>>();

    // output projection (HMMA)
    gemm_hmma<<<dim3(HID / 128, S_LEN / 128), 256, GH_SMEM>>>(bhi, blo, woh, wol, out, S_LEN, HID, HID);
}